// round 8
// baseline (speedup 1.0000x reference)
#include <cuda_runtime.h>
#include <cuda_bf16.h>
#include <cfloat>
#include <cstdint>

// Problem constants (fixed by setup_inputs)
#define BATCH 32
#define CH    512
#define TLEN  128
#define NROI  128
#define OBINS 64
#define BINSZ 8                              // CH / OBINS
#define NROIS_TOTAL (BATCH * NROI)           // 4096
#define POOLED_ELEMS (NROIS_TOTAL * OBINS)   // 262144

#define SPLIT_O 8                            // o-groups per batch
#define OB (OBINS / SPLIT_O)                 // 8 bins per block (1 per warp)
#define NTHREADS 256
#define LVPITCH 132                          // floats between levels (528 B, 16B-mult)
#define CHUNK_BYTES 4096                     // per-warp contiguous feature slice

__device__ __forceinline__ float4 f4max(float4 a, float4 b) {
    float4 r;
    r.x = fmaxf(a.x, b.x); r.y = fmaxf(a.y, b.y);
    r.z = fmaxf(a.z, b.z); r.w = fmaxf(a.w, b.w);
    return r;
}

__device__ __forceinline__ uint32_t smem_u32(const void* p) {
    return (uint32_t)__cvta_generic_to_shared(p);
}

__device__ __forceinline__ void mbar_wait_parity0(uint32_t mbar) {
    asm volatile(
        "{\n\t"
        ".reg .pred P;\n\t"
        "WL_%=:\n\t"
        "mbarrier.try_wait.parity.shared.b64 P, [%0], 0, 0x989680;\n\t"
        "@P bra.uni WD_%=;\n\t"
        "bra.uni WL_%=;\n\t"
        "WD_%=:\n\t"
        "}" :: "r"(mbar) : "memory");
}

// Fused, warp-autonomous, TMA-fed. Grid = 32x8 = 256 blocks, 256 threads.
// Warp w owns bin og*8+w whose 8 channels are a CONTIGUOUS 4 KB gmem chunk.
// Lane 0 issues a cp.async.bulk of that chunk into the warp's smem region;
// the warp sleeps on its private mbarrier, folds channels from smem, builds
// sparse range-max levels L0..L4 in registers via shuffles, stores them back
// over its own input region, then answers each ROI with 2 lookups + 1 fmax.
__global__ void __launch_bounds__(NTHREADS, 4)
roipool_fused(const float* __restrict__ feat,
              const int* __restrict__ tois,
              float* __restrict__ out) {
    const int tid = threadIdx.x;
    const int w   = tid >> 5;                // warp = bin within group
    const int l   = tid & 31;                // lane = t-quad
    const int b   = blockIdx.x >> 3;         // batch
    const int og  = blockIdx.x & 7;          // bin-group

    __shared__ alignas(16) float inp[OB][1024];   // 32 KB: input, then levels
    __shared__ float st[NROI * (OB + 1)];         // staging [rl][o] pitch 9
    __shared__ alignas(8) unsigned long long mbar[OB];

    const uint32_t mb  = smem_u32(&mbar[w]);
    const uint32_t dst = smem_u32(&inp[w][0]);
    const float* src = feat + (size_t)(b * CH + (og * OB + w) * BINSZ) * TLEN;

    // ---- per-warp TMA bulk copy of this bin's 4 KB chunk ----
    if (l == 0) {
        asm volatile("mbarrier.init.shared.b64 [%0], 1;" :: "r"(mb) : "memory");
        asm volatile("fence.proxy.async.shared::cta;" ::: "memory");
    }
    __syncwarp();
    if (l == 0) {
        asm volatile("mbarrier.arrive.expect_tx.shared.b64 _, [%0], %1;"
                     :: "r"(mb), "r"((uint32_t)CHUNK_BYTES) : "memory");
        asm volatile("cp.async.bulk.shared::cta.global.mbarrier::complete_tx::bytes"
                     " [%0], [%1], %2, [%3];"
                     :: "r"(dst), "l"(src), "r"((uint32_t)CHUNK_BYTES), "r"(mb)
                     : "memory");
    }
    mbar_wait_parity0(mb);

    // ---- Phase 1: fold 8 channels from smem (LDS.128, conflict-free) ----
    const float4* q = (const float4*)&inp[w][0] + l;   // + c*32 per channel
    float4 v0 = q[0 * 32], v1 = q[1 * 32], v2 = q[2 * 32], v3 = q[3 * 32];
    float4 v4 = q[4 * 32], v5 = q[5 * 32], v6 = q[6 * 32], v7 = q[7 * 32];
    float4 a = f4max(f4max(f4max(v0, v1), f4max(v2, v3)),
                     f4max(f4max(v4, v5), f4max(v6, v7)));   // L0[4l..4l+3]

    // ---- sparse-max levels in registers via shuffles ----
    const unsigned FULL = 0xffffffffu;
    float nx = __shfl_down_sync(FULL, a.x, 1);
    float4 bq = make_float4(fmaxf(a.x, a.y), fmaxf(a.y, a.z),
                            fmaxf(a.z, a.w), fmaxf(a.w, nx));
    float nb0 = __shfl_down_sync(FULL, bq.x, 1);
    float nb1 = __shfl_down_sync(FULL, bq.y, 1);
    float4 cq = make_float4(fmaxf(bq.x, bq.z), fmaxf(bq.y, bq.w),
                            fmaxf(bq.z, nb0), fmaxf(bq.w, nb1));
    float4 nc;
    nc.x = __shfl_down_sync(FULL, cq.x, 1); nc.y = __shfl_down_sync(FULL, cq.y, 1);
    nc.z = __shfl_down_sync(FULL, cq.z, 1); nc.w = __shfl_down_sync(FULL, cq.w, 1);
    float4 dq = f4max(cq, nc);
    float4 nd;
    nd.x = __shfl_down_sync(FULL, dq.x, 2); nd.y = __shfl_down_sync(FULL, dq.y, 2);
    nd.z = __shfl_down_sync(FULL, dq.z, 2); nd.w = __shfl_down_sync(FULL, dq.w, 2);
    float4 eq = f4max(dq, nd);
    // (Clamped-shuffle garbage only at t > 128-2^k, never queried.)

    // ---- store levels over our own input region (all input now in regs) ----
    __syncwarp();
    *(float4*)&inp[w][0 * LVPITCH + 4 * l] = a;
    *(float4*)&inp[w][1 * LVPITCH + 4 * l] = bq;
    *(float4*)&inp[w][2 * LVPITCH + 4 * l] = cq;
    *(float4*)&inp[w][3 * LVPITCH + 4 * l] = dq;
    *(float4*)&inp[w][4 * LVPITCH + 4 * l] = eq;
    __syncwarp();

    // ---- Phase 2: 128 ROIs for this bin, 4 per lane, 2 lookups each ----
    const int2* tp = (const int2*)(tois) + b * NROI;
#pragma unroll
    for (int i = 0; i < 4; i++) {
        const int rl = l + 32 * i;
        const int2 se = __ldg(&tp[rl]);
        const int len = se.y - se.x;         // 1..16
        const int k = 31 - __clz(len);       // floor(log2 len), 0..4
        const float* Lk = &inp[w][k * LVPITCH];
        float m = fmaxf(Lk[se.x], Lk[se.y - (1 << k)]);
        st[rl * (OB + 1) + w] = m;
    }
    __syncthreads();

    // ---- Coalescing writeout: 1024 floats, 4 per thread ----
#pragma unroll
    for (int idx = tid; idx < NROI * OB; idx += NTHREADS) {
        const int rl = idx >> 3;
        const int o  = idx & 7;
        out[(size_t)(b * NROI + rl) * OBINS + og * OB + o] = st[rl * (OB + 1) + o];
    }

    // ---- offsets tail (float-encoded in the unified f32 output buffer) ----
    if (blockIdx.x == 0 && tid < BATCH) {
        out[POOLED_ELEMS + tid] = (float)((tid + 1) * NROI);
    }
}

extern "C" void kernel_launch(void* const* d_in, const int* in_sizes, int n_in,
                              void* d_out, int out_size) {
    const float* feat = (const float*)d_in[0];   // [32, 512, 128] f32
    const int*   tois = (const int*)d_in[1];     // [32, 128, 2] i32
    float* out = (float*)d_out;

    roipool_fused<<<BATCH * SPLIT_O, NTHREADS>>>(feat, tois, out);
}